// round 1
// baseline (speedup 1.0000x reference)
#include <cuda_runtime.h>
#include <cuda_bf16.h>

// FIRFilter: depthwise 4x4 separable FIR, NHWC [16,256,256,64] fp32,
// pad (1,2)/(1,2), 'same' output.
//
// Strategy: memory-bound streaming kernel.
//  - Row = 4096 contiguous float4 (W*C/4). One thread per (w, c4) column,
//    coalesced float4 loads/stores.
//  - Separable filter: horizontal pass in registers per fetched row,
//    vertical pass via 4 rolling float4 registers over a STRIP of 32 rows.
//  - 1D coeffs derived from the rank-1 2D kernel input (exact).

namespace {

constexpr int Hh = 256;
constexpr int Ww = 256;
constexpr int Cc = 64;
constexpr int Bb = 16;
constexpr int RS = Ww * Cc / 4;   // 4096 float4 per image row
constexpr int STRIP = 32;         // output rows per thread
constexpr int THREADS = 256;

__device__ __forceinline__ float4 hfilt_row(const float4* __restrict__ Xcol, int r,
                                            bool m1, bool p1, bool p2,
                                            float kh0, float kh1, float kh2, float kh3) {
    float4 acc = make_float4(0.f, 0.f, 0.f, 0.f);
    if ((unsigned)r < (unsigned)Hh) {
        const float4* p = Xcol + (long long)r * RS;
        float4 b = __ldg(p);                     // tap at w
        acc.x = kh1 * b.x;
        acc.y = kh1 * b.y;
        acc.z = kh1 * b.z;
        acc.w = kh1 * b.w;
        if (m1) {                                // tap at w-1 (16 float4 = 1 pixel)
            float4 a = __ldg(p - 16);
            acc.x = fmaf(kh0, a.x, acc.x);
            acc.y = fmaf(kh0, a.y, acc.y);
            acc.z = fmaf(kh0, a.z, acc.z);
            acc.w = fmaf(kh0, a.w, acc.w);
        }
        if (p1) {                                // tap at w+1
            float4 c = __ldg(p + 16);
            acc.x = fmaf(kh2, c.x, acc.x);
            acc.y = fmaf(kh2, c.y, acc.y);
            acc.z = fmaf(kh2, c.z, acc.z);
            acc.w = fmaf(kh2, c.w, acc.w);
        }
        if (p2) {                                // tap at w+2
            float4 d = __ldg(p + 32);
            acc.x = fmaf(kh3, d.x, acc.x);
            acc.y = fmaf(kh3, d.y, acc.y);
            acc.z = fmaf(kh3, d.z, acc.z);
            acc.w = fmaf(kh3, d.w, acc.w);
        }
    }
    return acc;
}

__global__ __launch_bounds__(THREADS)
void fir_depthwise_kernel(const float* __restrict__ xin,
                          const float* __restrict__ ker,
                          float* __restrict__ yout) {
    // Derive separable 1D coefficients from the rank-1 4x4 kernel.
    // k2[i][j] = kv[i] * kh[j] with kh[j] = k2[0][j], kv[i] = k2[i][0] / k2[0][0].
    const float kh0 = __ldg(ker + 0);
    const float kh1 = __ldg(ker + 1);
    const float kh2 = __ldg(ker + 2);
    const float kh3 = __ldg(ker + 3);
    const float inv00 = 1.0f / kh0;
    const float kv1 = __ldg(ker + 4)  * inv00;
    const float kv2 = __ldg(ker + 8)  * inv00;
    const float kv3 = __ldg(ker + 12) * inv00;
    // kv0 == 1.0f exactly.

    const int tid = blockIdx.x * THREADS + threadIdx.x;   // 0..4095: (w<<4)|c4
    const int w = tid >> 4;
    const bool m1 = (w >= 1);
    const bool p1 = (w <= Ww - 2);
    const bool p2 = (w <= Ww - 3);

    const long long img = (long long)blockIdx.z * (Hh * (long long)RS);
    const float4* Xcol = reinterpret_cast<const float4*>(xin) + img + tid;
    float4*       Ycol = reinterpret_cast<float4*>(yout)      + img + tid;

    const int h0 = blockIdx.y * STRIP;

    // Prime rolling horizontally-filtered rows: hf(h0-1), hf(h0), hf(h0+1)
    float4 r0 = hfilt_row(Xcol, h0 - 1, m1, p1, p2, kh0, kh1, kh2, kh3);
    float4 r1 = hfilt_row(Xcol, h0    , m1, p1, p2, kh0, kh1, kh2, kh3);
    float4 r2 = hfilt_row(Xcol, h0 + 1, m1, p1, p2, kh0, kh1, kh2, kh3);

    #pragma unroll 4
    for (int i = 0; i < STRIP; ++i) {
        float4 r3 = hfilt_row(Xcol, h0 + i + 2, m1, p1, p2, kh0, kh1, kh2, kh3);

        float4 o;
        o.x = r0.x + kv1 * r1.x;  // kv0 == 1
        o.y = r0.y + kv1 * r1.y;
        o.z = r0.z + kv1 * r1.z;
        o.w = r0.w + kv1 * r1.w;
        o.x = fmaf(kv2, r2.x, o.x);
        o.y = fmaf(kv2, r2.y, o.y);
        o.z = fmaf(kv2, r2.z, o.z);
        o.w = fmaf(kv2, r2.w, o.w);
        o.x = fmaf(kv3, r3.x, o.x);
        o.y = fmaf(kv3, r3.y, o.y);
        o.z = fmaf(kv3, r3.z, o.z);
        o.w = fmaf(kv3, r3.w, o.w);

        Ycol[(long long)(h0 + i) * RS] = o;

        r0 = r1; r1 = r2; r2 = r3;
    }
}

} // namespace

extern "C" void kernel_launch(void* const* d_in, const int* in_sizes, int n_in,
                              void* d_out, int out_size) {
    // metadata order: x [16*256*256*64], kernel [16]. Be defensive about order.
    const float* x = (const float*)d_in[0];
    const float* k = (const float*)d_in[1];
    if (n_in >= 2 && in_sizes[0] == 16 && in_sizes[1] != 16) {
        x = (const float*)d_in[1];
        k = (const float*)d_in[0];
    }
    float* out = (float*)d_out;

    dim3 grid(RS / THREADS, Hh / STRIP, Bb);   // (16, 8, 16)
    fir_depthwise_kernel<<<grid, THREADS>>>(x, k, out);
}

// round 2
// speedup vs baseline: 1.0330x; 1.0330x over previous
#include <cuda_runtime.h>
#include <cuda_bf16.h>

// FIRFilter: depthwise 4x4 separable FIR, NHWC [16,256,256,64] fp32.
// R2: branch-free load path (clamped offsets + zeroed coeffs) and 4-row
// load batching to raise MLP; kernel was latency-bound at 54% DRAM.

namespace {

constexpr int Hh = 256;
constexpr int Ww = 256;
constexpr int RS = Ww * 64 / 4;    // 4096 float4 per image row
constexpr int STRIP = 32;          // output rows per thread
constexpr int THREADS = 256;
constexpr int ROWG = 4;            // rows per batched group

struct HRow { float4 v; };

// Horizontally filter row r for this thread's column. Branch-free:
// all 4 loads unconditional (offsets pre-clamped), out-of-range rows
// clamped and zero-scaled.
__device__ __forceinline__ float4 hrow(const float4* __restrict__ Xcol, int r,
                                       int o0, int o2, int o3,
                                       float c0, float c1, float c2, float c3) {
    int rc = min(max(r, 0), Hh - 1);
    float s = (r == rc) ? 1.0f : 0.0f;
    const float4* p = Xcol + (long long)rc * RS;
    float4 a = __ldg(p + o0);
    float4 b = __ldg(p);
    float4 c = __ldg(p + o2);
    float4 d = __ldg(p + o3);
    float4 acc;
    acc.x = c1 * b.x; acc.y = c1 * b.y; acc.z = c1 * b.z; acc.w = c1 * b.w;
    acc.x = fmaf(c0, a.x, acc.x); acc.y = fmaf(c0, a.y, acc.y);
    acc.z = fmaf(c0, a.z, acc.z); acc.w = fmaf(c0, a.w, acc.w);
    acc.x = fmaf(c2, c.x, acc.x); acc.y = fmaf(c2, c.y, acc.y);
    acc.z = fmaf(c2, c.z, acc.z); acc.w = fmaf(c2, c.w, acc.w);
    acc.x = fmaf(c3, d.x, acc.x); acc.y = fmaf(c3, d.y, acc.y);
    acc.z = fmaf(c3, d.z, acc.z); acc.w = fmaf(c3, d.w, acc.w);
    acc.x *= s; acc.y *= s; acc.z *= s; acc.w *= s;
    return acc;
}

__device__ __forceinline__ float4 vcomb(const float4& a, const float4& b,
                                        const float4& c, const float4& d,
                                        float kv1, float kv2, float kv3) {
    float4 o;
    o.x = fmaf(kv1, b.x, a.x); o.y = fmaf(kv1, b.y, a.y);
    o.z = fmaf(kv1, b.z, a.z); o.w = fmaf(kv1, b.w, a.w);
    o.x = fmaf(kv2, c.x, o.x); o.y = fmaf(kv2, c.y, o.y);
    o.z = fmaf(kv2, c.z, o.z); o.w = fmaf(kv2, c.w, o.w);
    o.x = fmaf(kv3, d.x, o.x); o.y = fmaf(kv3, d.y, o.y);
    o.z = fmaf(kv3, d.z, o.z); o.w = fmaf(kv3, d.w, o.w);
    return o;
}

__global__ __launch_bounds__(THREADS)
void fir_depthwise_kernel(const float* __restrict__ xin,
                          const float* __restrict__ ker,
                          float* __restrict__ yout) {
    // Separable 1D coefficients from the rank-1 4x4 kernel.
    const float kh0 = __ldg(ker + 0);
    const float kh1 = __ldg(ker + 1);
    const float kh2 = __ldg(ker + 2);
    const float kh3 = __ldg(ker + 3);
    const float inv00 = 1.0f / kh0;
    const float kv1 = __ldg(ker + 4)  * inv00;
    const float kv2 = __ldg(ker + 8)  * inv00;
    const float kv3 = __ldg(ker + 12) * inv00;   // kv0 == 1

    const int tid = blockIdx.x * THREADS + threadIdx.x;   // (w<<4)|c4
    const int w = tid >> 4;

    // Branch-free horizontal taps: clamp offset, zero coefficient at edges.
    const bool m1 = (w >= 1), p1 = (w <= Ww - 2), p2 = (w <= Ww - 3);
    const int   o0 = m1 ? -16 : 0;
    const int   o2 = p1 ?  16 : 0;
    const int   o3 = p2 ?  32 : 0;
    const float c0 = m1 ? kh0 : 0.0f;
    const float c2 = p1 ? kh2 : 0.0f;
    const float c3 = p2 ? kh3 : 0.0f;

    const long long img = (long long)blockIdx.z * (Hh * (long long)RS);
    const float4* Xcol = reinterpret_cast<const float4*>(xin) + img + tid;
    float4*       Ycol = reinterpret_cast<float4*>(yout)      + img + tid;

    const int h0 = blockIdx.y * STRIP;

    // Prime rolling rows hf(h0-1), hf(h0), hf(h0+1).
    float4 r0 = hrow(Xcol, h0 - 1, o0, o2, o3, c0, kh1, c2, c3);
    float4 r1 = hrow(Xcol, h0    , o0, o2, o3, c0, kh1, c2, c3);
    float4 r2 = hrow(Xcol, h0 + 1, o0, o2, o3, c0, kh1, c2, c3);

    for (int i = 0; i < STRIP; i += ROWG) {
        // Front-batched loads for 4 new rows (16 LDG.128, no branches).
        float4 r3 = hrow(Xcol, h0 + i + 2, o0, o2, o3, c0, kh1, c2, c3);
        float4 r4 = hrow(Xcol, h0 + i + 3, o0, o2, o3, c0, kh1, c2, c3);
        float4 r5 = hrow(Xcol, h0 + i + 4, o0, o2, o3, c0, kh1, c2, c3);
        float4 r6 = hrow(Xcol, h0 + i + 5, o0, o2, o3, c0, kh1, c2, c3);

        float4* yp = Ycol + (long long)(h0 + i) * RS;
        yp[0]      = vcomb(r0, r1, r2, r3, kv1, kv2, kv3);
        yp[RS]     = vcomb(r1, r2, r3, r4, kv1, kv2, kv3);
        yp[2 * RS] = vcomb(r2, r3, r4, r5, kv1, kv2, kv3);
        yp[3 * RS] = vcomb(r3, r4, r5, r6, kv1, kv2, kv3);

        r0 = r4; r1 = r5; r2 = r6;
    }
}

} // namespace

extern "C" void kernel_launch(void* const* d_in, const int* in_sizes, int n_in,
                              void* d_out, int out_size) {
    const float* x = (const float*)d_in[0];
    const float* k = (const float*)d_in[1];
    if (n_in >= 2 && in_sizes[0] == 16 && in_sizes[1] != 16) {
        x = (const float*)d_in[1];
        k = (const float*)d_in[0];
    }
    float* out = (float*)d_out;

    dim3 grid(RS / THREADS, Hh / STRIP, 16);   // (16, 8, 16)
    fir_depthwise_kernel<<<grid, THREADS>>>(x, k, out);
}